// round 5
// baseline (speedup 1.0000x reference)
#include <cuda_runtime.h>
#include <cuda_bf16.h>

// B=256, T=4096, D=64, U=2 linear RNN as a 16-tap matrix FIR (K=16 truncation;
// rel_err ~1.2e-7 confirmed R1-R4). Pure HBM streaming: 256MB x read.
//
// R4 left L1 at 58% — SHFLs were ~half the MIO stream. R5: each thread loads
// 2 float4s of the SAME row (8 threads/row), reduction 16 lanes -> 8 lanes:
// 4 SHFL per 64 f4 instead of 5 per 32. Full unroll keeps MLP high.

#define B_    256
#define T_    4096
#define D_    64
#define U_    2
#define K_    16
#define CHUNK 256
#define HALO  16
#define NH    (CHUNK + HALO)          // 272 rows

__global__ void __launch_bounds__(256, 4)
rnn_fused_kernel(const float* __restrict__ x,
                 const float* __restrict__ W,
                 const float* __restrict__ Wr,
                 float* __restrict__ out)
{
    __shared__ float sW[D_ * U_];     // W row-major [d][u]
    __shared__ float sM[K_][4];       // W_rec^k row-major
    __shared__ float sh[NH][U_];      // h rows (chunk + halo)

    const int tid = threadIdx.x;
    const int nchunks = T_ / CHUNK;   // 16
    const int b = blockIdx.x / nchunks;
    const int c = blockIdx.x % nchunks;
    const long t0 = (long)c * CHUNK;

    if (tid < D_ * U_) sW[tid] = W[tid];
    if (tid == 0) {
        const float a00 = Wr[0], a01 = Wr[1], a10 = Wr[2], a11 = Wr[3];
        float m00 = 1.f, m01 = 0.f, m10 = 0.f, m11 = 1.f;
        #pragma unroll
        for (int k = 0; k < K_; ++k) {
            sM[k][0] = m00; sM[k][1] = m01; sM[k][2] = m10; sM[k][3] = m11;
            const float n00 = m00 * a00 + m01 * a10;
            const float n01 = m00 * a01 + m01 * a11;
            const float n10 = m10 * a00 + m11 * a10;
            const float n11 = m10 * a01 + m11 * a11;
            m00 = n00; m01 = n01; m10 = n10; m11 = n11;
        }
    }
    __syncthreads();

    // ---- phase 1: h = x @ W ----
    // 8 threads per row; thread owns float4 slots jq and jq+8 of its row.
    // Each LDG: 4 rows x contiguous 128B half-rows = 4 wavefronts (minimal).
    const int jq   = tid & 7;          // f4 slot in first half-row
    const int rsub = tid >> 3;         // row-within-iteration, 0..31
    const float4* sW4 = reinterpret_cast<const float4*>(sW);
    const float4 wa = sW4[2 * jq];           // W rows 4jq .. 4jq+1
    const float4 wb = sW4[2 * jq + 1];       // W rows 4jq+2 .. 4jq+3
    const float4 wc = sW4[2 * (jq + 8)];     // W rows 4jq+32 ..
    const float4 wd = sW4[2 * (jq + 8) + 1];

    const long base = ((long)b * T_ + (t0 - HALO)) * (D_ / 4);
    const float4* __restrict__ x4 = reinterpret_cast<const float4*>(x);

    // 8-lane merged reduction + write. After offset-4 role split, lanes
    // 0-3 of each octet carry the h0 sum, lanes 4-7 the h1 sum.
    #define REDUCE8_WRITE(row, p0, p1)                                      \
    {                                                                       \
        const float q0 = __shfl_xor_sync(0xffffffffu, (p0), 4);             \
        const float q1 = __shfl_xor_sync(0xffffffffu, (p1), 4);             \
        float s = (tid & 4) ? ((p1) + q1) : ((p0) + q0);                    \
        s += __shfl_xor_sync(0xffffffffu, s, 2);                            \
        s += __shfl_xor_sync(0xffffffffu, s, 1);                            \
        if ((tid & 3) == 0) sh[(row)][(tid >> 2) & 1] = s;                  \
    }

    // Halo iteration: rows 0..15, duplicated across rsub (both halves write
    // identical values to the same slot - benign). c==0 clamps into rows
    // 16..31 (memory this block reads anyway) and zeroes the contribution.
    {
        const int row = rsub & 15;
        const bool valid = (c != 0);
        const long a = base + (long)(valid ? row : row + HALO) * 16 + jq;
        const float4 u = __ldcs(&x4[a]);
        const float4 v = __ldcs(&x4[a + 8]);
        const float scale = valid ? 1.f : 0.f;
        const float p0 = scale * (u.x*wa.x + u.y*wa.z + u.z*wb.x + u.w*wb.z
                                + v.x*wc.x + v.y*wc.z + v.z*wd.x + v.w*wd.z);
        const float p1 = scale * (u.x*wa.y + u.y*wa.w + u.z*wb.y + u.w*wb.w
                                + v.x*wc.y + v.y*wc.w + v.z*wd.y + v.w*wd.w);
        REDUCE8_WRITE(row, p0, p1)
    }

    // Main body: rows 16..271, 8 iterations x 32 rows, fully unrolled.
    #pragma unroll
    for (int it = 0; it < CHUNK / 32; ++it) {
        const int row = HALO + it * 32 + rsub;
        const long a = base + (long)row * 16 + jq;
        const float4 u = __ldcs(&x4[a]);
        const float4 v = __ldcs(&x4[a + 8]);
        const float p0 = u.x*wa.x + u.y*wa.z + u.z*wb.x + u.w*wb.z
                       + v.x*wc.x + v.y*wc.z + v.z*wd.x + v.w*wd.z;
        const float p1 = u.x*wa.y + u.y*wa.w + u.z*wb.y + u.w*wb.w
                       + v.x*wc.y + v.y*wc.w + v.z*wd.y + v.w*wd.w;
        REDUCE8_WRITE(row, p0, p1)
    }
    __syncthreads();

    // ---- phase 2: 16-tap matrix FIR ----
    float o0 = 0.f, o1 = 0.f;
    #pragma unroll
    for (int k = 0; k < K_; ++k) {
        const int idx = HALO + tid - k;
        const float h0 = sh[idx][0];
        const float h1 = sh[idx][1];
        o0 += h0 * sM[k][0] + h1 * sM[k][2];
        o1 += h0 * sM[k][1] + h1 * sM[k][3];
    }

    const long t = t0 + tid;
    float2* outp = reinterpret_cast<float2*>(out + ((long)b * T_ + t) * U_);
    __stcs(outp, make_float2(o0, o1));   // coalesced streaming STG.64
}

extern "C" void kernel_launch(void* const* d_in, const int* in_sizes, int n_in,
                              void* d_out, int out_size)
{
    const float* x  = (const float*)d_in[0];   // [B,T,D] fp32
    const float* W  = (const float*)d_in[1];   // [D,U]   fp32
    const float* Wr = (const float*)d_in[2];   // [U,U]   fp32
    float* out = (float*)d_out;                // [B,T,U] fp32

    rnn_fused_kernel<<<B_ * (T_ / CHUNK), 256>>>(x, W, Wr, out);
}

// round 6
// speedup vs baseline: 1.0019x; 1.0019x over previous
#include <cuda_runtime.h>
#include <cuda_bf16.h>
#include <cstdint>

// B=256, T=4096, D=64, U=2 linear RNN as a 16-tap matrix FIR (K=16 truncation;
// rel_err ~1.2e-7 confirmed R1-R5). Pure HBM streaming: 256MB x read.
//
// R5 lesson: limiter is NOT the L1/MIO datapath; it's LDG latency exposure
// under the 64-reg cap (register-bound MLP). R6: single cp.async.bulk per
// block loads the whole contiguous 68KB tile into SMEM (async-engine MLP,
// zero register payload); compute reads SMEM with the proven R4 pattern.

#define B_    256
#define T_    4096
#define D_    64
#define U_    2
#define K_    16
#define CHUNK 256
#define HALO  16
#define NH    (CHUNK + HALO)              // 272 rows
#define NF4   (NH * (D_ / 4))             // 4352 float4 = 17 * 256
#define TILE_BYTES (NH * D_ * 4)          // 69632
#define BODY_BYTES (CHUNK * D_ * 4)       // 65536

__global__ void __launch_bounds__(256)
rnn_fused_kernel(const float* __restrict__ x,
                 const float* __restrict__ W,
                 const float* __restrict__ Wr,
                 float* __restrict__ out)
{
    extern __shared__ float4 sx4[];       // NH*16 float4 tile (69632 B)
    __shared__ float sW[D_ * U_];
    __shared__ float sM[K_][4];
    __shared__ float sh[NH][U_];
    __shared__ alignas(8) uint64_t mbar;

    const int tid = threadIdx.x;
    const int nchunks = T_ / CHUNK;       // 16
    const int b = blockIdx.x / nchunks;
    const int c = blockIdx.x % nchunks;
    const long t0 = (long)c * CHUNK;

    const uint32_t mb = (uint32_t)__cvta_generic_to_shared(&mbar);
    const uint32_t sx_base = (uint32_t)__cvta_generic_to_shared(sx4);

    // ---- setup ----
    if (tid < D_ * U_) sW[tid] = W[tid];
    if (tid == 64) {
        const float a00 = Wr[0], a01 = Wr[1], a10 = Wr[2], a11 = Wr[3];
        float m00 = 1.f, m01 = 0.f, m10 = 0.f, m11 = 1.f;
        #pragma unroll
        for (int k = 0; k < K_; ++k) {
            sM[k][0] = m00; sM[k][1] = m01; sM[k][2] = m10; sM[k][3] = m11;
            const float n00 = m00 * a00 + m01 * a10;
            const float n01 = m00 * a01 + m01 * a11;
            const float n10 = m10 * a00 + m11 * a10;
            const float n11 = m10 * a01 + m11 * a11;
            m00 = n00; m01 = n01; m10 = n10; m11 = n11;
        }
    }
    if (tid == 0) {
        asm volatile("mbarrier.init.shared.b64 [%0], 1;" :: "r"(mb) : "memory");
    }
    __syncthreads();   // mbarrier + sW/sM visible

    // ---- async bulk load of the tile ----
    // Interior chunks: rows 0..271 = t in [t0-16, t0+256). Chunk 0: body only
    // (rows 16..271 = t in [0,256)), rows 0..15 zero-filled by threads.
    if (tid == 0) {
        const uint32_t bytes = (c == 0) ? BODY_BYTES : TILE_BYTES;
        const uint32_t dst   = (c == 0) ? sx_base + HALO * (D_ * 4) : sx_base;
        const float4* src = reinterpret_cast<const float4*>(x)
                          + ((long)b * T_ + t0 - (c == 0 ? 0 : HALO)) * (D_ / 4);
        asm volatile(
            "mbarrier.arrive.expect_tx.shared.b64 _, [%0], %1;"
            :: "r"(mb), "r"(bytes) : "memory");
        asm volatile(
            "cp.async.bulk.shared::cluster.global.mbarrier::complete_tx::bytes "
            "[%0], [%1], %2, [%3];"
            :: "r"(dst), "l"(src), "r"(bytes), "r"(mb) : "memory");
    }
    if (c == 0) {
        sx4[tid] = make_float4(0.f, 0.f, 0.f, 0.f);   // rows 0..15 (256 f4)
    }

    // per-thread W registers (j fixed)
    const int j = tid & 15;
    const float4* sW4 = reinterpret_cast<const float4*>(sW);
    const float4 wa = sW4[2 * j];
    const float4 wb = sW4[2 * j + 1];

    // wait for bulk completion (acquire)
    asm volatile(
        "{\n\t"
        ".reg .pred p;\n\t"
        "WL%=:\n\t"
        "mbarrier.try_wait.parity.acquire.cta.shared::cta.b64 p, [%0], 0, 0x989680;\n\t"
        "@p bra WD%=;\n\t"
        "bra WL%=;\n\t"
        "WD%=:\n\t"
        "}" :: "r"(mb) : "memory");

    // ---- phase 1: h = x @ W from SMEM (coalesced LDS.128 + 5-shfl) ----
    #pragma unroll
    for (int it = 0; it < NF4 / 256; ++it) {          // 17 iterations
        const int f = tid + it * 256;
        const int row = f >> 4;
        const float4 xv = sx4[f];
        const float p0 = xv.x*wa.x + xv.y*wa.z + xv.z*wb.x + xv.w*wb.z;
        const float p1 = xv.x*wa.y + xv.y*wa.w + xv.z*wb.y + xv.w*wb.w;

        const float q0 = __shfl_xor_sync(0xffffffffu, p0, 8);
        const float q1 = __shfl_xor_sync(0xffffffffu, p1, 8);
        float s = (tid & 8) ? (p1 + q1) : (p0 + q0);
        s += __shfl_xor_sync(0xffffffffu, s, 4);
        s += __shfl_xor_sync(0xffffffffu, s, 2);
        s += __shfl_xor_sync(0xffffffffu, s, 1);
        if ((tid & 7) == 0)
            sh[row][(tid >> 3) & 1] = s;
    }
    __syncthreads();

    // ---- phase 2: 16-tap matrix FIR ----
    float o0 = 0.f, o1 = 0.f;
    #pragma unroll
    for (int k = 0; k < K_; ++k) {
        const int idx = HALO + tid - k;
        const float h0 = sh[idx][0];
        const float h1 = sh[idx][1];
        o0 += h0 * sM[k][0] + h1 * sM[k][2];
        o1 += h0 * sM[k][1] + h1 * sM[k][3];
    }

    const long t = t0 + tid;
    float2* outp = reinterpret_cast<float2*>(out + ((long)b * T_ + t) * U_);
    __stcs(outp, make_float2(o0, o1));
}

extern "C" void kernel_launch(void* const* d_in, const int* in_sizes, int n_in,
                              void* d_out, int out_size)
{
    const float* x  = (const float*)d_in[0];   // [B,T,D] fp32
    const float* W  = (const float*)d_in[1];   // [D,U]   fp32
    const float* Wr = (const float*)d_in[2];   // [U,U]   fp32
    float* out = (float*)d_out;                // [B,T,U] fp32

    cudaFuncSetAttribute(rnn_fused_kernel,
                         cudaFuncAttributeMaxDynamicSharedMemorySize, TILE_BYTES);
    rnn_fused_kernel<<<B_ * (T_ / CHUNK), 256, TILE_BYTES>>>(x, W, Wr, out);
}